// round 2
// baseline (speedup 1.0000x reference)
#include <cuda_runtime.h>
#include <cuda_bf16.h>

#define MAXN 500000
#define MAXE 500000
#define F 128

// ---------------- scratch (static device globals; no allocation) ----------------
__device__ float g_h[(size_t)MAXN * F];   // h = x @ W
__device__ float g_s[MAXN];               // per-node dot with a_src
__device__ float g_d[MAXN];               // per-node dot with a_dst
__device__ float g_alpha[MAXE];           // per-edge logits, then exp values
__device__ unsigned int g_max_u;          // encoded float max
__device__ float g_sum;                   // softmax denominator

// monotone float<->uint encoding for atomicMax on floats
__device__ __forceinline__ unsigned int enc_f(float f) {
    unsigned int u = __float_as_uint(f);
    return (u & 0x80000000u) ? ~u : (u | 0x80000000u);
}
__device__ __forceinline__ float dec_f(unsigned int u) {
    u = (u & 0x80000000u) ? (u & 0x7FFFFFFFu) : ~u;
    return __uint_as_float(u);
}

__device__ __forceinline__ float warpSum(float v) {
    #pragma unroll
    for (int o = 16; o > 0; o >>= 1) v += __shfl_xor_sync(0xFFFFFFFFu, v, o);
    return v;
}
__device__ __forceinline__ float warpMax(float v) {
    #pragma unroll
    for (int o = 16; o > 0; o >>= 1) v = fmaxf(v, __shfl_xor_sync(0xFFFFFFFFu, v, o));
    return v;
}

__global__ void init_kernel() {
    g_max_u = 0u;      // decodes below any real float's encoding
    g_sum = 0.0f;
}

// ---------------- K1: h = x @ W  (128x128 block tile, 8x8 per thread) ----------------
__global__ __launch_bounds__(256) void gemm_kernel(const float* __restrict__ x,
                                                   const float* __restrict__ w,
                                                   int N) {
    __shared__ float sW[32][F];    // 16 KB: K-slab of W
    __shared__ float sX[128][32];  // 16 KB: row tile of x

    const int tid = threadIdx.x;
    const int row0 = blockIdx.x * 128;
    const int tr = (tid >> 4) * 8;   // 0..120
    const int tc = (tid & 15) * 8;   // 0..120

    float acc[8][8];
    #pragma unroll
    for (int i = 0; i < 8; i++)
        #pragma unroll
        for (int j = 0; j < 8; j++) acc[i][j] = 0.0f;

    for (int kt = 0; kt < F; kt += 32) {
        // load W slab: 4096 floats = 1024 float4, 4 per thread
        #pragma unroll
        for (int i = 0; i < 4; i++) {
            int q = tid + i * 256;
            int kk = q >> 5;     // 0..31
            int c4 = q & 31;     // 0..31
            reinterpret_cast<float4*>(sW[kk])[c4] =
                reinterpret_cast<const float4*>(w)[(kt + kk) * 32 + c4];
        }
        // load x tile: 128 rows x 32 k = 1024 float4, 4 per thread
        #pragma unroll
        for (int i = 0; i < 4; i++) {
            int q = tid + i * 256;
            int r = q >> 3;      // 0..127
            int c4 = q & 7;      // 0..7
            int grow = row0 + r;
            float4 v = make_float4(0.f, 0.f, 0.f, 0.f);
            if (grow < N)
                v = reinterpret_cast<const float4*>(x)[(size_t)grow * 32 + (kt >> 2) + c4];
            reinterpret_cast<float4*>(sX[r])[c4] = v;
        }
        __syncthreads();

        #pragma unroll
        for (int kk = 0; kk < 32; kk++) {
            float bv[8];
            *reinterpret_cast<float4*>(bv)     = *reinterpret_cast<float4*>(&sW[kk][tc]);
            *reinterpret_cast<float4*>(bv + 4) = *reinterpret_cast<float4*>(&sW[kk][tc + 4]);
            #pragma unroll
            for (int r = 0; r < 8; r++) {
                float a = sX[tr + r][kk];
                #pragma unroll
                for (int j = 0; j < 8; j++) acc[r][j] = fmaf(a, bv[j], acc[r][j]);
            }
        }
        __syncthreads();
    }

    #pragma unroll
    for (int r = 0; r < 8; r++) {
        int grow = row0 + tr + r;
        if (grow < N) {
            float* dst = &g_h[(size_t)grow * F + tc];
            reinterpret_cast<float4*>(dst)[0] = *reinterpret_cast<float4*>(&acc[r][0]);
            reinterpret_cast<float4*>(dst)[1] = *reinterpret_cast<float4*>(&acc[r][4]);
        }
    }
}

// ---------------- K2: out[row[e]] += h[col[e]]  (one warp per edge) ----------------
__global__ __launch_bounds__(256) void scatter_kernel(const int* __restrict__ ei,
                                                      float* __restrict__ out, int E) {
    int e = (blockIdx.x * blockDim.x + threadIdx.x) >> 5;
    int lane = threadIdx.x & 31;
    if (e >= E) return;
    int r = ei[e];
    int c = ei[E + e];
    float4 v = reinterpret_cast<const float4*>(&g_h[(size_t)c * F])[lane];
    float* dst = out + (size_t)r * F + lane * 4;
    asm volatile("red.global.add.v4.f32 [%0], {%1,%2,%3,%4};"
                 :: "l"(dst), "f"(v.x), "f"(v.y), "f"(v.z), "f"(v.w)
                 : "memory");
}

// ---------------- K3: out = relu(out + bias); s[i], d[i] dots (one warp per node) ----------------
__global__ __launch_bounds__(256) void postproc_kernel(float* __restrict__ out,
                                                       const float* __restrict__ bias,
                                                       const float* __restrict__ att,
                                                       int N) {
    int node = (blockIdx.x * blockDim.x + threadIdx.x) >> 5;
    int lane = threadIdx.x & 31;
    if (node >= N) return;
    float4* rowp = reinterpret_cast<float4*>(out + (size_t)node * F);
    float4 v = rowp[lane];
    float4 b = reinterpret_cast<const float4*>(bias)[lane];
    v.x = fmaxf(v.x + b.x, 0.f);
    v.y = fmaxf(v.y + b.y, 0.f);
    v.z = fmaxf(v.z + b.z, 0.f);
    v.w = fmaxf(v.w + b.w, 0.f);
    rowp[lane] = v;
    float4 as = reinterpret_cast<const float4*>(att)[lane];       // a_src
    float4 ad = reinterpret_cast<const float4*>(att)[32 + lane];  // a_dst
    float ss = v.x * as.x + v.y * as.y + v.z * as.z + v.w * as.w;
    float dd = v.x * ad.x + v.y * ad.y + v.z * ad.z + v.w * ad.w;
    ss = warpSum(ss);
    dd = warpSum(dd);
    if (lane == 0) { g_s[node] = ss; g_d[node] = dd; }
}

// ---------------- K4: alpha[e] = leaky_relu(s[row]+d[col]); global max ----------------
__global__ __launch_bounds__(256) void alpha_kernel(const int* __restrict__ ei, int E) {
    const float NEG_INF = __int_as_float(0xff800000);
    int e = blockIdx.x * blockDim.x + threadIdx.x;
    int lane = threadIdx.x & 31;
    int wid = threadIdx.x >> 5;
    float a = NEG_INF;
    if (e < E) {
        int r = ei[e];
        int c = ei[E + e];
        float v = g_s[r] + g_d[c];
        a = (v > 0.f) ? v : 0.2f * v;
        g_alpha[e] = a;
    }
    __shared__ float smax[8];
    float m = warpMax(a);
    if (lane == 0) smax[wid] = m;
    __syncthreads();
    if (wid == 0) {
        float mm = (lane < 8) ? smax[lane] : NEG_INF;
        mm = warpMax(mm);
        if (lane == 0) atomicMax(&g_max_u, enc_f(mm));
    }
}

// ---------------- K5: alpha[e] = exp(alpha[e]-max); global sum ----------------
__global__ __launch_bounds__(256) void expsum_kernel(int E) {
    int e = blockIdx.x * blockDim.x + threadIdx.x;
    int lane = threadIdx.x & 31;
    int wid = threadIdx.x >> 5;
    float mx = dec_f(g_max_u);
    float v = 0.f;
    if (e < E) {
        v = __expf(g_alpha[e] - mx);
        g_alpha[e] = v;
    }
    __shared__ float ssum[8];
    float s = warpSum(v);
    if (lane == 0) ssum[wid] = s;
    __syncthreads();
    if (wid == 0) {
        float t = (lane < 8) ? ssum[lane] : 0.f;
        t = warpSum(t);
        if (lane == 0) atomicAdd(&g_sum, t);
    }
}

// ---------------- K6: out[i,:] *= alpha[i] / sum  (in place) ----------------
__global__ __launch_bounds__(256) void scale_kernel(float* __restrict__ out, int N) {
    size_t i = (size_t)blockIdx.x * blockDim.x + threadIdx.x;  // float4 index
    if (i >= (size_t)N * 32) return;
    int node = (int)(i >> 5);
    float sc = g_alpha[node] / g_sum;
    float4 v = reinterpret_cast<float4*>(out)[i];
    v.x *= sc; v.y *= sc; v.z *= sc; v.w *= sc;
    reinterpret_cast<float4*>(out)[i] = v;
}

extern "C" void kernel_launch(void* const* d_in, const int* in_sizes, int n_in,
                              void* d_out, int out_size) {
    const float* x   = (const float*)d_in[0];
    const int* ei    = (const int*)d_in[1];     // edge_index: int32 (JAX x64 disabled)
    const float* w   = (const float*)d_in[2];
    const float* att = (const float*)d_in[3];
    const float* bias= (const float*)d_in[4];
    float* out       = (float*)d_out;

    int N = in_sizes[0] / F;   // 500000
    int E = in_sizes[1] / 2;   // 500000

    cudaMemsetAsync(d_out, 0, (size_t)N * F * sizeof(float));
    init_kernel<<<1, 1>>>();
    gemm_kernel<<<(N + 127) / 128, 256>>>(x, w, N);
    scatter_kernel<<<(E + 7) / 8, 256>>>(ei, out, E);
    postproc_kernel<<<(N + 7) / 8, 256>>>(out, bias, att, N);
    alpha_kernel<<<(E + 255) / 256, 256>>>(ei, E);
    expsum_kernel<<<(E + 255) / 256, 256>>>(E);
    scale_kernel<<<(int)(((size_t)N * 32 + 255) / 256), 256>>>(out, N);
}

// round 4
// speedup vs baseline: 1.2903x; 1.2903x over previous
#include <cuda_runtime.h>
#include <mma.h>
#include <cstdint>

using namespace nvcuda;

#define MAXN 500000
#define MAXE 500000
#define F 128

// ---------------- scratch (static device globals; no allocation) ----------------
__device__ float g_h[(size_t)MAXN * F];   // h = x @ W
__device__ float g_s[MAXN];               // per-node dot with a_src
__device__ float g_d[MAXN];               // per-node dot with a_dst
__device__ float g_alpha[MAXE];           // per-edge logits, then exp values
__device__ unsigned int g_max_u;          // encoded float max
__device__ float g_sum;                   // softmax denominator

// ---------------- small helpers ----------------
__device__ __forceinline__ unsigned int enc_f(float f) {
    unsigned int u = __float_as_uint(f);
    return (u & 0x80000000u) ? ~u : (u | 0x80000000u);
}
__device__ __forceinline__ float dec_f(unsigned int u) {
    u = (u & 0x80000000u) ? (u & 0x7FFFFFFFu) : ~u;
    return __uint_as_float(u);
}
__device__ __forceinline__ float warpSum(float v) {
    #pragma unroll
    for (int o = 16; o > 0; o >>= 1) v += __shfl_xor_sync(0xFFFFFFFFu, v, o);
    return v;
}
__device__ __forceinline__ float warpMax(float v) {
    #pragma unroll
    for (int o = 16; o > 0; o >>= 1) v = fmaxf(v, __shfl_xor_sync(0xFFFFFFFFu, v, o));
    return v;
}

__global__ void init_kernel() {
    g_max_u = 0u;
    g_sum = 0.0f;
}

// ---------------- K1: h = x @ W via wmma tf32 (full 128-row tiles, no guards) ------
// CTA: 128x128 output tile, K=128. W staged in SMEM (ld=136). 8 warps = 4(M) x 2(N),
// warp tile 32x64 = 2x4 m16n16k8 fragments.
#define WLD 136
#define GSMEM_BYTES (128 * WLD * 4)   // 69632

__global__ __launch_bounds__(256) void gemm_mma_kernel(const float* __restrict__ x,
                                                       const float* __restrict__ w) {
    extern __shared__ float sW[];   // [128][WLD]
    const int tid = threadIdx.x;

    // Stage W (K x N row-major), converting to tf32 (rna) once.
    #pragma unroll
    for (int i = 0; i < 16; i++) {
        int q = tid + i * 256;        // float4 id: 32 per row
        int k = q >> 5;
        int c4 = q & 31;
        float4 v = reinterpret_cast<const float4*>(w)[k * 32 + c4];
        v.x = wmma::__float_to_tf32(v.x);
        v.y = wmma::__float_to_tf32(v.y);
        v.z = wmma::__float_to_tf32(v.z);
        v.w = wmma::__float_to_tf32(v.w);
        *reinterpret_cast<float4*>(&sW[k * WLD + c4 * 4]) = v;
    }
    __syncthreads();

    const int wid = tid >> 5;
    const int warp_m = wid & 3;          // 0..3
    const int warp_n = wid >> 2;         // 0..1
    const size_t m0 = (size_t)blockIdx.x * 128 + warp_m * 32;
    const int n0 = warp_n * 64;

    wmma::fragment<wmma::accumulator, 16, 16, 8, float> c[2][4];
    #pragma unroll
    for (int mi = 0; mi < 2; mi++)
        #pragma unroll
        for (int ni = 0; ni < 4; ni++) wmma::fill_fragment(c[mi][ni], 0.0f);

    #pragma unroll
    for (int kf = 0; kf < 16; kf++) {
        const int k = kf * 8;
        wmma::fragment<wmma::matrix_a, 16, 16, 8, wmma::precision::tf32, wmma::row_major> a[2];
        wmma::fragment<wmma::matrix_b, 16, 16, 8, wmma::precision::tf32, wmma::row_major> b[4];
        #pragma unroll
        for (int mi = 0; mi < 2; mi++) {
            wmma::load_matrix_sync(a[mi], x + (m0 + mi * 16) * F + k, F);
            #pragma unroll
            for (int t = 0; t < a[mi].num_elements; t++)
                a[mi].x[t] = wmma::__float_to_tf32(a[mi].x[t]);
        }
        #pragma unroll
        for (int ni = 0; ni < 4; ni++)
            wmma::load_matrix_sync(b[ni], &sW[k * WLD + n0 + ni * 16], WLD);
        #pragma unroll
        for (int mi = 0; mi < 2; mi++)
            #pragma unroll
            for (int ni = 0; ni < 4; ni++)
                wmma::mma_sync(c[mi][ni], a[mi], b[ni], c[mi][ni]);
    }

    #pragma unroll
    for (int mi = 0; mi < 2; mi++)
        #pragma unroll
        for (int ni = 0; ni < 4; ni++)
            wmma::store_matrix_sync(&g_h[(m0 + mi * 16) * F + n0 + ni * 16],
                                    c[mi][ni], F, wmma::mem_row_major);
}

// Tail rows [M0, N): one CTA per row, 128 threads (one per output col). Exact fp32.
__global__ __launch_bounds__(128) void gemm_tail_kernel(const float* __restrict__ x,
                                                        const float* __restrict__ w,
                                                        int M0, int N) {
    __shared__ float sx[F];
    int r = M0 + blockIdx.x;
    if (r >= N) return;
    sx[threadIdx.x] = x[(size_t)r * F + threadIdx.x];
    __syncthreads();
    float acc = 0.f;
    #pragma unroll 8
    for (int k = 0; k < F; k++) acc = fmaf(sx[k], w[k * F + threadIdx.x], acc);
    g_h[(size_t)r * F + threadIdx.x] = acc;
}

// ---------------- K2: out[row[e]] += h[col[e]]  (one warp per edge) ----------------
__global__ __launch_bounds__(256) void scatter_kernel(const int* __restrict__ ei,
                                                      float* __restrict__ out, int E) {
    int e = (blockIdx.x * blockDim.x + threadIdx.x) >> 5;
    int lane = threadIdx.x & 31;
    if (e >= E) return;
    int r = ei[e];
    int c = ei[E + e];
    float4 v = reinterpret_cast<const float4*>(&g_h[(size_t)c * F])[lane];
    float* dst = out + (size_t)r * F + lane * 4;
    asm volatile("red.global.add.v4.f32 [%0], {%1,%2,%3,%4};"
                 :: "l"(dst), "f"(v.x), "f"(v.y), "f"(v.z), "f"(v.w)
                 : "memory");
}

// ---------------- K3: s[i], d[i] from relu(out+bias) — READ ONLY on out ----------------
__global__ __launch_bounds__(256) void postproc_kernel(const float* __restrict__ out,
                                                       const float* __restrict__ bias,
                                                       const float* __restrict__ att,
                                                       int N) {
    int node = (blockIdx.x * blockDim.x + threadIdx.x) >> 5;
    int lane = threadIdx.x & 31;
    if (node >= N) return;
    float4 v = reinterpret_cast<const float4*>(out + (size_t)node * F)[lane];
    float4 b = reinterpret_cast<const float4*>(bias)[lane];
    v.x = fmaxf(v.x + b.x, 0.f);
    v.y = fmaxf(v.y + b.y, 0.f);
    v.z = fmaxf(v.z + b.z, 0.f);
    v.w = fmaxf(v.w + b.w, 0.f);
    float4 as = reinterpret_cast<const float4*>(att)[lane];       // a_src
    float4 ad = reinterpret_cast<const float4*>(att)[32 + lane];  // a_dst
    float ss = v.x * as.x + v.y * as.y + v.z * as.z + v.w * as.w;
    float dd = v.x * ad.x + v.y * ad.y + v.z * ad.z + v.w * ad.w;
    ss = warpSum(ss);
    dd = warpSum(dd);
    if (lane == 0) { g_s[node] = ss; g_d[node] = dd; }
}

// ---------------- K4: alpha[e] = leaky_relu(s[row]+d[col]); global max ----------------
__global__ __launch_bounds__(256) void alpha_kernel(const int* __restrict__ ei, int E) {
    const float NEG_INF = __int_as_float(0xff800000);
    int e = blockIdx.x * blockDim.x + threadIdx.x;
    int lane = threadIdx.x & 31;
    int wid = threadIdx.x >> 5;
    float a = NEG_INF;
    if (e < E) {
        int r = ei[e];
        int c = ei[E + e];
        float v = g_s[r] + g_d[c];
        a = (v > 0.f) ? v : 0.2f * v;
        g_alpha[e] = a;
    }
    __shared__ float smax[8];
    float m = warpMax(a);
    if (lane == 0) smax[wid] = m;
    __syncthreads();
    if (wid == 0) {
        float mm = (lane < 8) ? smax[lane] : NEG_INF;
        mm = warpMax(mm);
        if (lane == 0) atomicMax(&g_max_u, enc_f(mm));
    }
}

// ---------------- K5: alpha[e] = exp(alpha[e]-max); global sum ----------------
__global__ __launch_bounds__(256) void expsum_kernel(int E) {
    int e = blockIdx.x * blockDim.x + threadIdx.x;
    int lane = threadIdx.x & 31;
    int wid = threadIdx.x >> 5;
    float mx = dec_f(g_max_u);
    float v = 0.f;
    if (e < E) {
        v = __expf(g_alpha[e] - mx);
        g_alpha[e] = v;
    }
    __shared__ float ssum[8];
    float s = warpSum(v);
    if (lane == 0) ssum[wid] = s;
    __syncthreads();
    if (wid == 0) {
        float t = (lane < 8) ? ssum[lane] : 0.f;
        t = warpSum(t);
        if (lane == 0) atomicAdd(&g_sum, t);
    }
}

// ---------------- K6: out[i,:] = relu(out[i,:]+bias) * alpha[i]/sum (in place) -------
__global__ __launch_bounds__(256) void scale_kernel(float* __restrict__ out,
                                                    const float* __restrict__ bias,
                                                    int N) {
    size_t i = (size_t)blockIdx.x * blockDim.x + threadIdx.x;  // float4 index
    if (i >= (size_t)N * 32) return;
    int node = (int)(i >> 5);
    float sc = g_alpha[node] / g_sum;
    float4 v = reinterpret_cast<float4*>(out)[i];
    float4 b = reinterpret_cast<const float4*>(bias)[i & 31];
    v.x = fmaxf(v.x + b.x, 0.f) * sc;
    v.y = fmaxf(v.y + b.y, 0.f) * sc;
    v.z = fmaxf(v.z + b.z, 0.f) * sc;
    v.w = fmaxf(v.w + b.w, 0.f) * sc;
    reinterpret_cast<float4*>(out)[i] = v;
}

extern "C" void kernel_launch(void* const* d_in, const int* in_sizes, int n_in,
                              void* d_out, int out_size) {
    const float* x   = (const float*)d_in[0];
    const int* ei    = (const int*)d_in[1];     // edge_index: int32
    const float* w   = (const float*)d_in[2];
    const float* att = (const float*)d_in[3];
    const float* bias= (const float*)d_in[4];
    float* out       = (float*)d_out;

    int N = in_sizes[0] / F;   // 500000
    int E = in_sizes[1] / 2;   // 500000

    static int smem_set = 0;
    if (!smem_set) {
        cudaFuncSetAttribute(gemm_mma_kernel, cudaFuncAttributeMaxDynamicSharedMemorySize, GSMEM_BYTES);
        smem_set = 1;
    }

    int fullTiles = N / 128;           // 3906
    int M0 = fullTiles * 128;          // 499968
    int tailRows = N - M0;             // 32

    cudaMemsetAsync(d_out, 0, (size_t)N * F * sizeof(float));
    init_kernel<<<1, 1>>>();
    gemm_mma_kernel<<<fullTiles, 256, GSMEM_BYTES>>>(x, w);
    if (tailRows > 0) gemm_tail_kernel<<<tailRows, 128>>>(x, w, M0, N);
    scatter_kernel<<<(E + 7) / 8, 256>>>(ei, out, E);
    postproc_kernel<<<(N + 7) / 8, 256>>>(out, bias, att, N);
    alpha_kernel<<<(E + 255) / 256, 256>>>(ei, E);
    expsum_kernel<<<(E + 255) / 256, 256>>>(E);
    scale_kernel<<<(int)(((size_t)N * 32 + 255) / 256), 256>>>(out, bias, N);
}

// round 5
// speedup vs baseline: 1.4377x; 1.1142x over previous
#include <cuda_runtime.h>
#include <mma.h>
#include <cstdint>

using namespace nvcuda;

#define MAXN 500000
#define MAXE 500000
#define F 128

// ---------------- scratch (static device globals; no allocation) ----------------
__device__ float g_h[(size_t)MAXN * F];   // h = x @ W
__device__ float g_s[MAXN];               // per-node dot with a_src
__device__ float g_d[MAXN];               // per-node dot with a_dst
__device__ float g_alpha[MAXE];           // per-edge logits, then exp values
__device__ unsigned int g_max_u;          // encoded float max
__device__ float g_sum;                   // softmax denominator

// ---------------- small helpers ----------------
__device__ __forceinline__ unsigned int enc_f(float f) {
    unsigned int u = __float_as_uint(f);
    return (u & 0x80000000u) ? ~u : (u | 0x80000000u);
}
__device__ __forceinline__ float dec_f(unsigned int u) {
    u = (u & 0x80000000u) ? (u & 0x7FFFFFFFu) : ~u;
    return __uint_as_float(u);
}
__device__ __forceinline__ float warpSum(float v) {
    #pragma unroll
    for (int o = 16; o > 0; o >>= 1) v += __shfl_xor_sync(0xFFFFFFFFu, v, o);
    return v;
}
__device__ __forceinline__ float warpMax(float v) {
    #pragma unroll
    for (int o = 16; o > 0; o >>= 1) v = fmaxf(v, __shfl_xor_sync(0xFFFFFFFFu, v, o));
    return v;
}

__global__ void init_kernel() {
    g_max_u = 0u;
    g_sum = 0.0f;
}

// ---------------- K1: h = x @ W, persistent pipelined wmma-tf32 ----------------
// grid = NUM_SM CTAs, 256 threads. Each CTA stages W (tf32) once, then loops over
// 128-row tiles with double-buffered cp.async x-tile staging.
#define WLD 136
#define XLD 136
#define TILE_FLOATS (128 * XLD)
#define GSMEM_BYTES ((128 * WLD + 2 * TILE_FLOATS) * 4)   // 208,896 bytes

__device__ __forceinline__ uint32_t smem_u32(const void* p) {
    uint32_t a;
    asm("{ .reg .u64 t; cvta.to.shared.u64 t, %1; cvt.u32.u64 %0, t; }" : "=r"(a) : "l"(p));
    return a;
}

__device__ __forceinline__ void prefetch_tile(const float* __restrict__ x, int tile,
                                              float* dst, int tid) {
    const float4* src = reinterpret_cast<const float4*>(x + (size_t)tile * 128 * F);
    #pragma unroll
    for (int i = 0; i < 16; i++) {
        int q = tid + i * 256;
        int r = q >> 5;      // row 0..127
        int c4 = q & 31;     // float4 col
        uint32_t d = smem_u32(dst + r * XLD + c4 * 4);
        asm volatile("cp.async.cg.shared.global [%0], [%1], 16;" :: "r"(d), "l"(src + q) : "memory");
    }
    asm volatile("cp.async.commit_group;" ::: "memory");
}

__global__ __launch_bounds__(256) void gemm_mma_kernel(const float* __restrict__ x,
                                                       const float* __restrict__ w,
                                                       int numTiles) {
    extern __shared__ float smem[];
    float* sW = smem;                       // [128][WLD], tf32-converted
    float* sX0 = smem + 128 * WLD;
    float* sX1 = sX0 + TILE_FLOATS;
    const int tid = threadIdx.x;
    const int stride = gridDim.x;

    // Stage W (K x N row-major) once, converting to tf32 (rna).
    #pragma unroll
    for (int i = 0; i < 16; i++) {
        int q = tid + i * 256;
        int k = q >> 5;
        int c4 = q & 31;
        float4 v = reinterpret_cast<const float4*>(w)[k * 32 + c4];
        v.x = wmma::__float_to_tf32(v.x);
        v.y = wmma::__float_to_tf32(v.y);
        v.z = wmma::__float_to_tf32(v.z);
        v.w = wmma::__float_to_tf32(v.w);
        *reinterpret_cast<float4*>(&sW[k * WLD + c4 * 4]) = v;
    }

    int t0 = blockIdx.x;
    if (t0 < numTiles) prefetch_tile(x, t0, sX0, tid);

    const int wid = tid >> 5;
    const int warp_m = wid & 3;          // 0..3
    const int warp_n = wid >> 2;         // 0..1
    const int n0 = warp_n * 64;

    int buf = 0;
    for (int t = t0; t < numTiles; t += stride) {
        asm volatile("cp.async.wait_group 0;" ::: "memory");
        __syncthreads();    // x tile ready; also covers W staging on first iter

        int tn = t + stride;
        if (tn < numTiles) prefetch_tile(x, tn, buf ? sX0 : sX1, tid);

        const float* cur = buf ? sX1 : sX0;
        const float* aBase = cur + warp_m * 32 * XLD;

        wmma::fragment<wmma::accumulator, 16, 16, 8, float> c[2][4];
        #pragma unroll
        for (int mi = 0; mi < 2; mi++)
            #pragma unroll
            for (int ni = 0; ni < 4; ni++) wmma::fill_fragment(c[mi][ni], 0.0f);

        #pragma unroll
        for (int kf = 0; kf < 16; kf++) {
            const int k = kf * 8;
            wmma::fragment<wmma::matrix_a, 16, 16, 8, wmma::precision::tf32, wmma::row_major> a[2];
            wmma::fragment<wmma::matrix_b, 16, 16, 8, wmma::precision::tf32, wmma::row_major> b[4];
            #pragma unroll
            for (int mi = 0; mi < 2; mi++) {
                wmma::load_matrix_sync(a[mi], aBase + mi * 16 * XLD + k, XLD);
                #pragma unroll
                for (int e = 0; e < a[mi].num_elements; e++)
                    a[mi].x[e] = wmma::__float_to_tf32(a[mi].x[e]);
            }
            #pragma unroll
            for (int ni = 0; ni < 4; ni++)
                wmma::load_matrix_sync(b[ni], &sW[k * WLD + n0 + ni * 16], WLD);
            #pragma unroll
            for (int mi = 0; mi < 2; mi++)
                #pragma unroll
                for (int ni = 0; ni < 4; ni++)
                    wmma::mma_sync(c[mi][ni], a[mi], b[ni], c[mi][ni]);
        }

        const size_t m0 = (size_t)t * 128 + warp_m * 32;
        #pragma unroll
        for (int mi = 0; mi < 2; mi++)
            #pragma unroll
            for (int ni = 0; ni < 4; ni++)
                wmma::store_matrix_sync(&g_h[(m0 + mi * 16) * F + n0 + ni * 16],
                                        c[mi][ni], F, wmma::mem_row_major);
        buf ^= 1;
    }
}

// Tail rows [M0, N): one CTA per row, 128 threads (one per output col). Exact fp32.
__global__ __launch_bounds__(128) void gemm_tail_kernel(const float* __restrict__ x,
                                                        const float* __restrict__ w,
                                                        int M0, int N) {
    __shared__ float sx[F];
    int r = M0 + blockIdx.x;
    if (r >= N) return;
    sx[threadIdx.x] = x[(size_t)r * F + threadIdx.x];
    __syncthreads();
    float acc = 0.f;
    #pragma unroll 8
    for (int k = 0; k < F; k++) acc = fmaf(sx[k], w[k * F + threadIdx.x], acc);
    g_h[(size_t)r * F + threadIdx.x] = acc;
}

// ---------------- K2: out[row[e]] += h[col[e]]  (one warp per edge) ----------------
__global__ __launch_bounds__(256) void scatter_kernel(const int* __restrict__ ei,
                                                      float* __restrict__ out, int E) {
    int e = (blockIdx.x * blockDim.x + threadIdx.x) >> 5;
    int lane = threadIdx.x & 31;
    if (e >= E) return;
    int r = ei[e];
    int c = ei[E + e];
    float4 v = reinterpret_cast<const float4*>(&g_h[(size_t)c * F])[lane];
    float* dst = out + (size_t)r * F + lane * 4;
    asm volatile("red.global.add.v4.f32 [%0], {%1,%2,%3,%4};"
                 :: "l"(dst), "f"(v.x), "f"(v.y), "f"(v.z), "f"(v.w)
                 : "memory");
}

// ---------------- K3: s[i], d[i] from relu(out+bias) — READ ONLY on out ----------------
__global__ __launch_bounds__(256) void postproc_kernel(const float* __restrict__ out,
                                                       const float* __restrict__ bias,
                                                       const float* __restrict__ att,
                                                       int N) {
    int node = (blockIdx.x * blockDim.x + threadIdx.x) >> 5;
    int lane = threadIdx.x & 31;
    if (node >= N) return;
    float4 v = reinterpret_cast<const float4*>(out + (size_t)node * F)[lane];
    float4 b = reinterpret_cast<const float4*>(bias)[lane];
    v.x = fmaxf(v.x + b.x, 0.f);
    v.y = fmaxf(v.y + b.y, 0.f);
    v.z = fmaxf(v.z + b.z, 0.f);
    v.w = fmaxf(v.w + b.w, 0.f);
    float4 as = reinterpret_cast<const float4*>(att)[lane];       // a_src
    float4 ad = reinterpret_cast<const float4*>(att)[32 + lane];  // a_dst
    float ss = v.x * as.x + v.y * as.y + v.z * as.z + v.w * as.w;
    float dd = v.x * ad.x + v.y * ad.y + v.z * ad.z + v.w * ad.w;
    ss = warpSum(ss);
    dd = warpSum(dd);
    if (lane == 0) { g_s[node] = ss; g_d[node] = dd; }
}

// ---------------- K4: alpha[e] = leaky_relu(s[row]+d[col]); global max ----------------
__global__ __launch_bounds__(256) void alpha_kernel(const int* __restrict__ ei, int E) {
    const float NEG_INF = __int_as_float(0xff800000);
    int e = blockIdx.x * blockDim.x + threadIdx.x;
    int lane = threadIdx.x & 31;
    int wid = threadIdx.x >> 5;
    float a = NEG_INF;
    if (e < E) {
        int r = ei[e];
        int c = ei[E + e];
        float v = g_s[r] + g_d[c];
        a = (v > 0.f) ? v : 0.2f * v;
        g_alpha[e] = a;
    }
    __shared__ float smax[8];
    float m = warpMax(a);
    if (lane == 0) smax[wid] = m;
    __syncthreads();
    if (wid == 0) {
        float mm = (lane < 8) ? smax[lane] : NEG_INF;
        mm = warpMax(mm);
        if (lane == 0) atomicMax(&g_max_u, enc_f(mm));
    }
}

// ---------------- K5: alpha[e] = exp(alpha[e]-max); global sum ----------------
__global__ __launch_bounds__(256) void expsum_kernel(int E) {
    int e = blockIdx.x * blockDim.x + threadIdx.x;
    int lane = threadIdx.x & 31;
    int wid = threadIdx.x >> 5;
    float mx = dec_f(g_max_u);
    float v = 0.f;
    if (e < E) {
        v = __expf(g_alpha[e] - mx);
        g_alpha[e] = v;
    }
    __shared__ float ssum[8];
    float s = warpSum(v);
    if (lane == 0) ssum[wid] = s;
    __syncthreads();
    if (wid == 0) {
        float t = (lane < 8) ? ssum[lane] : 0.f;
        t = warpSum(t);
        if (lane == 0) atomicAdd(&g_sum, t);
    }
}

// ---------------- K6: out[i,:] = relu(out[i,:]+bias) * alpha[i]/sum (in place) -------
__global__ __launch_bounds__(256) void scale_kernel(float* __restrict__ out,
                                                    const float* __restrict__ bias,
                                                    int N) {
    size_t i = (size_t)blockIdx.x * blockDim.x + threadIdx.x;  // float4 index
    if (i >= (size_t)N * 32) return;
    int node = (int)(i >> 5);
    float sc = g_alpha[node] / g_sum;
    float4 v = reinterpret_cast<float4*>(out)[i];
    float4 b = reinterpret_cast<const float4*>(bias)[i & 31];
    v.x = fmaxf(v.x + b.x, 0.f) * sc;
    v.y = fmaxf(v.y + b.y, 0.f) * sc;
    v.z = fmaxf(v.z + b.z, 0.f) * sc;
    v.w = fmaxf(v.w + b.w, 0.f) * sc;
    reinterpret_cast<float4*>(out)[i] = v;
}

extern "C" void kernel_launch(void* const* d_in, const int* in_sizes, int n_in,
                              void* d_out, int out_size) {
    const float* x   = (const float*)d_in[0];
    const int* ei    = (const int*)d_in[1];     // edge_index: int32
    const float* w   = (const float*)d_in[2];
    const float* att = (const float*)d_in[3];
    const float* bias= (const float*)d_in[4];
    float* out       = (float*)d_out;

    int N = in_sizes[0] / F;   // 500000
    int E = in_sizes[1] / 2;   // 500000

    static int smem_set = 0;
    if (!smem_set) {
        cudaFuncSetAttribute(gemm_mma_kernel, cudaFuncAttributeMaxDynamicSharedMemorySize, GSMEM_BYTES);
        smem_set = 1;
    }

    int fullTiles = N / 128;           // 3906
    int M0 = fullTiles * 128;          // 499968
    int tailRows = N - M0;             // 32
    int gemmGrid = 152;                // GB300: 152 SMs
    if (gemmGrid > fullTiles) gemmGrid = fullTiles;

    cudaMemsetAsync(d_out, 0, (size_t)N * F * sizeof(float));
    init_kernel<<<1, 1>>>();
    gemm_mma_kernel<<<gemmGrid, 256, GSMEM_BYTES>>>(x, w, fullTiles);
    if (tailRows > 0) gemm_tail_kernel<<<tailRows, 128>>>(x, w, M0, N);
    scatter_kernel<<<(E + 7) / 8, 256>>>(ei, out, E);
    postproc_kernel<<<(N + 7) / 8, 256>>>(out, bias, att, N);
    alpha_kernel<<<(E + 255) / 256, 256>>>(ei, E);
    expsum_kernel<<<(E + 255) / 256, 256>>>(E);
    scale_kernel<<<(int)(((size_t)N * 32 + 255) / 256), 256>>>(out, bias, N);
}